// round 2
// baseline (speedup 1.0000x reference)
#include <cuda_runtime.h>

#define KTOT 16
#define CDIM 32
#define TRI  528          // 32*33/2
#define NVOX (2*96*96*64) // 1179648
#define VPT  4            // voxels per thread
#define TPB  128

// ---------------- scratch (device globals; no allocation allowed) ----------
static __device__ float g_tri[KTOT * TRI];   // Linv, lower-tri packed row-major
static __device__ float g_b[KTOT * CDIM];    // b_k = Linv_k @ mu_k
static __device__ float g_a[KTOT];           // a_k = w_k * exp((const - logdet_k)/200)

// ---------------- f32x2 helpers -------------------------------------------
__device__ __forceinline__ unsigned long long pack2(float a, float b) {
    unsigned long long r;
    asm("mov.b64 %0, {%1, %2};" : "=l"(r) : "f"(a), "f"(b));
    return r;
}
__device__ __forceinline__ unsigned long long dup2(float a) { return pack2(a, a); }
__device__ __forceinline__ unsigned long long fma2(unsigned long long a,
                                                   unsigned long long b,
                                                   unsigned long long c) {
    unsigned long long d;
    asm("fma.rn.f32x2 %0, %1, %2, %3;" : "=l"(d) : "l"(a), "l"(b), "l"(c));
    return d;
}
__device__ __forceinline__ void unpack2(unsigned long long v, float& a, float& b) {
    asm("mov.b64 {%0, %1}, %2;" : "=f"(a), "=f"(b) : "l"(v));
}

// ---------------- kernel 1: invert the 16 lower-triangular Cholesky factors
// thread (k, j) computes column j of Linv_k by forward substitution.
__global__ void invert_kernel(const float* __restrict__ Lbg,
                              const float* __restrict__ Lfg) {
    int tid = blockIdx.x * blockDim.x + threadIdx.x;
    if (tid >= KTOT * CDIM) return;
    int k = tid / CDIM, j = tid % CDIM;
    const float* L = (k < 8) ? (Lbg + k * CDIM * CDIM)
                             : (Lfg + (k - 8) * CDIM * CDIM);
    float v[CDIM];
    v[j] = 1.0f / L[j * CDIM + j];
    for (int i = j + 1; i < CDIM; ++i) {
        float s = 0.0f;
        for (int m = j; m < i; ++m) s += L[i * CDIM + m] * v[m];
        v[i] = -s / L[i * CDIM + i];
    }
    float* tk = g_tri + k * TRI;
    for (int i = j; i < CDIM; ++i) tk[i * (i + 1) / 2 + j] = v[i];
}

// ---------------- kernel 2: b_k = Linv_k @ mu_k ; a_k scalar ---------------
__global__ void prep_kernel(const float* __restrict__ wbg,
                            const float* __restrict__ mubg,
                            const float* __restrict__ Lbg,
                            const float* __restrict__ wfg,
                            const float* __restrict__ mufg,
                            const float* __restrict__ Lfg) {
    int tid = blockIdx.x * blockDim.x + threadIdx.x;
    if (tid >= KTOT * CDIM) return;
    int k = tid / CDIM, d = tid % CDIM;
    const float* mu = (k < 8) ? (mubg + k * CDIM) : (mufg + (k - 8) * CDIM);
    const float* row = g_tri + k * TRI + d * (d + 1) / 2;
    float s = 0.0f;
    for (int c = 0; c <= d; ++c) s += row[c] * mu[c];
    g_b[k * CDIM + d] = s;

    if (d == 0) {
        const float* L = (k < 8) ? (Lbg + k * CDIM * CDIM)
                                 : (Lfg + (k - 8) * CDIM * CDIM);
        float ld = 0.0f;
        for (int i = 0; i < CDIM; ++i) ld += logf(L[i * CDIM + i]);
        float w = (k < 8) ? wbg[k] : wfg[k - 8];
        const float cst = -0.5f * 32.0f * 1.8378770664093453f; // -C/2*log(2pi)
        g_a[k] = w * expf((cst - ld) * (1.0f / 200.0f));
    }
}

// ---------------- kernel 3: main density kernel ----------------------------
// 4 voxels per thread, packed as two f32x2 pairs. Triangular Linv in smem,
// broadcast LDS. dens = sum_k a_k * exp(-||Linv x - b||^2 / 400).
__global__ void __launch_bounds__(TPB)
density_kernel(const float* __restrict__ fm, float* __restrict__ out) {
    __shared__ float s_tri[KTOT * TRI];
    __shared__ float s_b[KTOT * CDIM];
    __shared__ float s_a[KTOT];

    for (int i = threadIdx.x; i < KTOT * TRI; i += TPB) s_tri[i] = g_tri[i];
    for (int i = threadIdx.x; i < KTOT * CDIM; i += TPB) s_b[i] = g_b[i];
    if (threadIdx.x < KTOT) s_a[threadIdx.x] = g_a[threadIdx.x];
    __syncthreads();

    long long vb = (long long)(blockIdx.x * TPB + threadIdx.x) * VPT;
    if (vb >= NVOX) return;

    // Load 4 voxels' features (32 floats each) and pack into f32x2 pairs.
    const float4* f4 = (const float4*)(fm + vb * CDIM);
    unsigned long long xp01[CDIM], xp23[CDIM];
#pragma unroll
    for (int j = 0; j < 8; ++j) {
        float4 q0 = f4[j];
        float4 q1 = f4[8 + j];
        float4 q2 = f4[16 + j];
        float4 q3 = f4[24 + j];
        xp01[4 * j + 0] = pack2(q0.x, q1.x);
        xp01[4 * j + 1] = pack2(q0.y, q1.y);
        xp01[4 * j + 2] = pack2(q0.z, q1.z);
        xp01[4 * j + 3] = pack2(q0.w, q1.w);
        xp23[4 * j + 0] = pack2(q2.x, q3.x);
        xp23[4 * j + 1] = pack2(q2.y, q3.y);
        xp23[4 * j + 2] = pack2(q2.z, q3.z);
        xp23[4 * j + 3] = pack2(q2.w, q3.w);
    }

    float dens0 = 0.f, dens1 = 0.f, dens2 = 0.f, dens3 = 0.f;

#pragma unroll 1
    for (int k = 0; k < KTOT; ++k) {
        const float* tk = s_tri + k * TRI;
        const float* bk = s_b + k * CDIM;
        unsigned long long acc01 = 0ull;  // packed (0.f, 0.f)
        unsigned long long acc23 = 0ull;
#pragma unroll
        for (int d = 0; d < CDIM; ++d) {
            unsigned long long y01 = dup2(-bk[d]);
            unsigned long long y23 = y01;
            const float* row = tk + d * (d + 1) / 2;
#pragma unroll
            for (int c = 0; c <= d; ++c) {
                unsigned long long l2 = dup2(row[c]);
                y01 = fma2(l2, xp01[c], y01);
                y23 = fma2(l2, xp23[c], y23);
            }
            acc01 = fma2(y01, y01, acc01);
            acc23 = fma2(y23, y23, acc23);
        }
        float a0, a1, a2, a3;
        unpack2(acc01, a0, a1);
        unpack2(acc23, a2, a3);
        float ak = s_a[k];
        dens0 += ak * __expf(a0 * -0.0025f);
        dens1 += ak * __expf(a1 * -0.0025f);
        dens2 += ak * __expf(a2 * -0.0025f);
        dens3 += ak * __expf(a3 * -0.0025f);
    }

    // z-mask: last z-slice (z == 63) stays zero. Z = 64 so z = voxel & 63.
    float4 o;
    o.x = (((vb + 0) & 63) == 63) ? 0.f : dens0;
    o.y = (((vb + 1) & 63) == 63) ? 0.f : dens1;
    o.z = (((vb + 2) & 63) == 63) ? 0.f : dens2;
    o.w = (((vb + 3) & 63) == 63) ? 0.f : dens3;
    *(float4*)(out + vb) = o;
}

// ---------------- launch ---------------------------------------------------
extern "C" void kernel_launch(void* const* d_in, const int* in_sizes, int n_in,
                              void* d_out, int out_size) {
    const float* fm   = (const float*)d_in[0];
    const float* wbg  = (const float*)d_in[1];
    const float* mubg = (const float*)d_in[2];
    const float* Lbg  = (const float*)d_in[3];
    const float* wfg  = (const float*)d_in[4];
    const float* mufg = (const float*)d_in[5];
    const float* Lfg  = (const float*)d_in[6];
    float* out = (float*)d_out;

    invert_kernel<<<1, KTOT * CDIM>>>(Lbg, Lfg);
    prep_kernel<<<1, KTOT * CDIM>>>(wbg, mubg, Lbg, wfg, mufg, Lfg);

    int threads = NVOX / VPT;             // 294912
    int blocks = (threads + TPB - 1) / TPB; // 2304
    density_kernel<<<blocks, TPB>>>(fm, out);
}

// round 3
// speedup vs baseline: 1.0081x; 1.0081x over previous
#include <cuda_runtime.h>

#define KTOT 16
#define CDIM 32
#define TRI  528          // 32*33/2
#define NVOX (2*96*96*64) // 1179648
#define VPT  4            // voxels per thread
#define TPB  128

// ---------------- scratch (device globals; no allocation allowed) ----------
static __device__ float g_tri[KTOT * TRI];   // Linv, lower-tri packed row-major
static __device__ float g_b[KTOT * CDIM];    // b_k = Linv_k @ mu_k
static __device__ float g_a[KTOT];           // a_k = w_k * exp((const - logdet_k)/200)

// ---------------- f32x2 helpers -------------------------------------------
__device__ __forceinline__ unsigned long long pack2(float a, float b) {
    unsigned long long r;
    asm("mov.b64 %0, {%1, %2};" : "=l"(r) : "f"(a), "f"(b));
    return r;
}
__device__ __forceinline__ unsigned long long dup2(float a) { return pack2(a, a); }
__device__ __forceinline__ unsigned long long fma2(unsigned long long a,
                                                   unsigned long long b,
                                                   unsigned long long c) {
    unsigned long long d;
    asm("fma.rn.f32x2 %0, %1, %2, %3;" : "=l"(d) : "l"(a), "l"(b), "l"(c));
    return d;
}
__device__ __forceinline__ void unpack2(unsigned long long v, float& a, float& b) {
    asm("mov.b64 {%0, %1}, %2;" : "=f"(a), "=f"(b) : "l"(v));
}

// ---------------- kernel 1: invert the 16 lower-triangular Cholesky factors
// thread (k, j) computes column j of Linv_k by forward substitution.
__global__ void invert_kernel(const float* __restrict__ Lbg,
                              const float* __restrict__ Lfg) {
    int tid = blockIdx.x * blockDim.x + threadIdx.x;
    if (tid >= KTOT * CDIM) return;
    int k = tid / CDIM, j = tid % CDIM;
    const float* L = (k < 8) ? (Lbg + k * CDIM * CDIM)
                             : (Lfg + (k - 8) * CDIM * CDIM);
    float v[CDIM];
    v[j] = 1.0f / L[j * CDIM + j];
    for (int i = j + 1; i < CDIM; ++i) {
        float s = 0.0f;
        for (int m = j; m < i; ++m) s += L[i * CDIM + m] * v[m];
        v[i] = -s / L[i * CDIM + i];
    }
    float* tk = g_tri + k * TRI;
    for (int i = j; i < CDIM; ++i) tk[i * (i + 1) / 2 + j] = v[i];
}

// ---------------- kernel 2: b_k = Linv_k @ mu_k ; a_k scalar ---------------
__global__ void prep_kernel(const float* __restrict__ wbg,
                            const float* __restrict__ mubg,
                            const float* __restrict__ Lbg,
                            const float* __restrict__ wfg,
                            const float* __restrict__ mufg,
                            const float* __restrict__ Lfg) {
    int tid = blockIdx.x * blockDim.x + threadIdx.x;
    if (tid >= KTOT * CDIM) return;
    int k = tid / CDIM, d = tid % CDIM;
    const float* mu = (k < 8) ? (mubg + k * CDIM) : (mufg + (k - 8) * CDIM);
    const float* row = g_tri + k * TRI + d * (d + 1) / 2;
    float s = 0.0f;
    for (int c = 0; c <= d; ++c) s += row[c] * mu[c];
    g_b[k * CDIM + d] = s;

    if (d == 0) {
        const float* L = (k < 8) ? (Lbg + k * CDIM * CDIM)
                                 : (Lfg + (k - 8) * CDIM * CDIM);
        float ld = 0.0f;
        for (int i = 0; i < CDIM; ++i) ld += logf(L[i * CDIM + i]);
        float w = (k < 8) ? wbg[k] : wfg[k - 8];
        const float cst = -0.5f * 32.0f * 1.8378770664093453f; // -C/2*log(2pi)
        g_a[k] = w * expf((cst - ld) * (1.0f / 200.0f));
    }
}

// ---------------- kernel 3: main density kernel ----------------------------
// 4 voxels per thread, packed as two f32x2 pairs. Triangular Linv in smem,
// broadcast LDS. dens = sum_k a_k * exp(-||Linv x - b||^2 / 400).
__global__ void __launch_bounds__(TPB)
density_kernel(const float* __restrict__ fm, float* __restrict__ out) {
    __shared__ float s_tri[KTOT * TRI];
    __shared__ float s_b[KTOT * CDIM];
    __shared__ float s_a[KTOT];

    for (int i = threadIdx.x; i < KTOT * TRI; i += TPB) s_tri[i] = g_tri[i];
    for (int i = threadIdx.x; i < KTOT * CDIM; i += TPB) s_b[i] = g_b[i];
    if (threadIdx.x < KTOT) s_a[threadIdx.x] = g_a[threadIdx.x];
    __syncthreads();

    long long vb = (long long)(blockIdx.x * TPB + threadIdx.x) * VPT;
    if (vb >= NVOX) return;

    // Load 4 voxels' features (32 floats each) and pack into f32x2 pairs.
    const float4* f4 = (const float4*)(fm + vb * CDIM);
    unsigned long long xp01[CDIM], xp23[CDIM];
#pragma unroll
    for (int j = 0; j < 8; ++j) {
        float4 q0 = f4[j];
        float4 q1 = f4[8 + j];
        float4 q2 = f4[16 + j];
        float4 q3 = f4[24 + j];
        xp01[4 * j + 0] = pack2(q0.x, q1.x);
        xp01[4 * j + 1] = pack2(q0.y, q1.y);
        xp01[4 * j + 2] = pack2(q0.z, q1.z);
        xp01[4 * j + 3] = pack2(q0.w, q1.w);
        xp23[4 * j + 0] = pack2(q2.x, q3.x);
        xp23[4 * j + 1] = pack2(q2.y, q3.y);
        xp23[4 * j + 2] = pack2(q2.z, q3.z);
        xp23[4 * j + 3] = pack2(q2.w, q3.w);
    }

    float dens0 = 0.f, dens1 = 0.f, dens2 = 0.f, dens3 = 0.f;

#pragma unroll 1
    for (int k = 0; k < KTOT; ++k) {
        const float* tk = s_tri + k * TRI;
        const float* bk = s_b + k * CDIM;
        unsigned long long acc01 = 0ull;  // packed (0.f, 0.f)
        unsigned long long acc23 = 0ull;
#pragma unroll
        for (int d = 0; d < CDIM; ++d) {
            unsigned long long y01 = dup2(-bk[d]);
            unsigned long long y23 = y01;
            const float* row = tk + d * (d + 1) / 2;
#pragma unroll
            for (int c = 0; c <= d; ++c) {
                unsigned long long l2 = dup2(row[c]);
                y01 = fma2(l2, xp01[c], y01);
                y23 = fma2(l2, xp23[c], y23);
            }
            acc01 = fma2(y01, y01, acc01);
            acc23 = fma2(y23, y23, acc23);
        }
        float a0, a1, a2, a3;
        unpack2(acc01, a0, a1);
        unpack2(acc23, a2, a3);
        float ak = s_a[k];
        dens0 += ak * __expf(a0 * -0.0025f);
        dens1 += ak * __expf(a1 * -0.0025f);
        dens2 += ak * __expf(a2 * -0.0025f);
        dens3 += ak * __expf(a3 * -0.0025f);
    }

    // z-mask: last z-slice (z == 63) stays zero. Z = 64 so z = voxel & 63.
    float4 o;
    o.x = (((vb + 0) & 63) == 63) ? 0.f : dens0;
    o.y = (((vb + 1) & 63) == 63) ? 0.f : dens1;
    o.z = (((vb + 2) & 63) == 63) ? 0.f : dens2;
    o.w = (((vb + 3) & 63) == 63) ? 0.f : dens3;
    *(float4*)(out + vb) = o;
}

// ---------------- launch ---------------------------------------------------
extern "C" void kernel_launch(void* const* d_in, const int* in_sizes, int n_in,
                              void* d_out, int out_size) {
    const float* fm   = (const float*)d_in[0];
    const float* wbg  = (const float*)d_in[1];
    const float* mubg = (const float*)d_in[2];
    const float* Lbg  = (const float*)d_in[3];
    const float* wfg  = (const float*)d_in[4];
    const float* mufg = (const float*)d_in[5];
    const float* Lfg  = (const float*)d_in[6];
    float* out = (float*)d_out;

    invert_kernel<<<1, KTOT * CDIM>>>(Lbg, Lfg);
    prep_kernel<<<1, KTOT * CDIM>>>(wbg, mubg, Lbg, wfg, mufg, Lfg);

    int threads = NVOX / VPT;             // 294912
    int blocks = (threads + TPB - 1) / TPB; // 2304
    density_kernel<<<blocks, TPB>>>(fm, out);
}

// round 5
// speedup vs baseline: 2.4073x; 2.3879x over previous
#include <cuda_runtime.h>
#include <cuda_fp16.h>
#include <cstdint>

#define NVOX   (2*96*96*64)   // 1179648
#define TPB    128
#define NTILES (NVOX / TPB)   // 9216
#define KCOMP  16
#define NFEAT  576
#define NKSTEP 36             // 576 / 16
#define NCHUNK 9              // 576 / 64

static __device__ float g_Wtmp[KCOMP * NFEAT];
static __device__ uint2 g_Wfrag[NKSTEP * 2 * 32];  // [kstep][ntile][lane] B fragments
static __device__ float g_a2[KCOMP];

// ---------------- PTX helpers ----------------------------------------------
__device__ __forceinline__ uint32_t smem_u32(const void* p) {
    uint32_t a;
    asm("{ .reg .u64 t; cvta.to.shared.u64 t, %1; cvt.u32.u64 %0, t; }"
        : "=r"(a) : "l"(p));
    return a;
}
#define STS128(r0, r1, r2, r3, a) \
    asm volatile("st.shared.v4.b32 [%0], {%1, %2, %3, %4};" \
                 :: "r"(a), "r"(r0), "r"(r1), "r"(r2), "r"(r3) : "memory")

__device__ __forceinline__ void ldm4(uint32_t* r, uint32_t addr) {
    asm volatile("ldmatrix.sync.aligned.m8n8.x4.shared.b16 {%0,%1,%2,%3}, [%4];"
        : "=r"(r[0]), "=r"(r[1]), "=r"(r[2]), "=r"(r[3]) : "r"(addr));
}
__device__ __forceinline__ void mma16816(float* d, const uint32_t* a,
                                         const uint32_t* b, const float* c) {
    asm volatile("mma.sync.aligned.m16n8k16.row.col.f32.f16.f16.f32 "
        "{%0,%1,%2,%3}, {%4,%5,%6,%7}, {%8,%9}, {%10,%11,%12,%13};"
        : "=f"(d[0]), "=f"(d[1]), "=f"(d[2]), "=f"(d[3])
        : "r"(a[0]), "r"(a[1]), "r"(a[2]), "r"(a[3]),
          "r"(b[0]), "r"(b[1]),
          "f"(c[0]), "f"(c[1]), "f"(c[2]), "f"(c[3]));
}

// ---------------- prep1: one block per component ---------------------------
// 32 threads; lane j computes column j of Linv by register-resident forward
// substitution, then the W coefficients for this component.
__global__ void prep1_kernel(const float* __restrict__ wbg,  const float* __restrict__ mubg,
                             const float* __restrict__ Lbg,  const float* __restrict__ wfg,
                             const float* __restrict__ mufg, const float* __restrict__ Lfg) {
    __shared__ float sL[1024];
    __shared__ float tk[528];
    __shared__ float sb[32];
    int k = blockIdx.x;
    int j = threadIdx.x;
    const float* L  = (k < 8) ? (Lbg  + k * 1024) : (Lfg  + (k - 8) * 1024);
    const float* mu = (k < 8) ? (mubg + k * 32)   : (mufg + (k - 8) * 32);
    for (int i = j; i < 1024; i += 32) sL[i] = L[i];
    __syncwarp();

    // forward substitution, vv fully in registers (compile-time indices)
    float vv[32];
#pragma unroll
    for (int r = 0; r < 32; ++r) {
        float s = 0.0f;
#pragma unroll
        for (int m = 0; m < r; ++m) s += sL[r * 32 + m] * vv[m];
        float diag = sL[r * 32 + r];
        vv[r] = (r < j) ? 0.0f : ((r == j) ? 1.0f / diag : -s / diag);
    }
    for (int r = j; r < 32; ++r) tk[r * (r + 1) / 2 + j] = vv[r];
    __syncthreads();

    // b_j = (Linv mu)_j
    float bj = 0.0f;
    {
        const float* row = tk + j * (j + 1) / 2;
        for (int c = 0; c <= j; ++c) bj += row[c] * mu[c];
    }
    sb[j] = bj;
    __syncthreads();

    const float inv400 = 0.0025f;
    // linear coeff: +2 (Linv^T b)_j / 400
    float q = 0.0f;
    for (int d = j; d < 32; ++d) q += tk[d * (d + 1) / 2 + j] * sb[d];
    g_Wtmp[k * NFEAT + 528 + j] = 2.0f * q * inv400;
    if (j < 16) g_Wtmp[k * NFEAT + 560 + j] = 0.0f;

    // quadratic coeffs: entry e -> (i, jj), coeff = -(2-delta) P_ij / 400
    for (int e = j; e < 528; e += 32) {
        int i = (int)((sqrtf(8.0f * e + 1.0f) - 1.0f) * 0.5f);
        while ((i + 1) * (i + 2) / 2 <= e) ++i;
        while (i * (i + 1) / 2 > e) --i;
        int jj = e - i * (i + 1) / 2;
        float p = 0.0f;
        for (int d = i; d < 32; ++d)
            p += tk[d * (d + 1) / 2 + i] * tk[d * (d + 1) / 2 + jj];
        g_Wtmp[k * NFEAT + e] = ((jj == i) ? -p : -2.0f * p) * inv400;
    }

    if (j == 0) {
        float ld = 0.0f, c0 = 0.0f;
        for (int d = 0; d < 32; ++d) { ld += logf(sL[d * 32 + d]); c0 += sb[d] * sb[d]; }
        float w = (k < 8) ? wbg[k] : wfg[k - 8];
        const float cst = -0.5f * 32.0f * 1.8378770664093453f;
        g_a2[k] = w * expf((cst - ld) * 0.005f - c0 * inv400);
    }
}

// ---------------- prep2: pack W into mma B-fragment layout -----------------
__global__ void prep2_kernel() {
    int idx = blockIdx.x * blockDim.x + threadIdx.x;
    if (idx >= NKSTEP * 64) return;
    int s = idx >> 6, rem = idx & 63, nt = rem >> 5, lane = rem & 31;
    int n = nt * 8 + (lane >> 2);
    int t0 = s * 16 + (lane & 3) * 2;
    const float* W = g_Wtmp + n * NFEAT;
    __half2 lo = __floats2half2_rn(W[t0], W[t0 + 1]);
    __half2 hi = __floats2half2_rn(W[t0 + 8], W[t0 + 9]);
    uint2 u;
    u.x = *(uint32_t*)&lo;
    u.y = *(uint32_t*)&hi;
    g_Wfrag[idx] = u;
}

// ---------------- density: quadratic-feature GEMM on HMMA ------------------
__global__ void __launch_bounds__(TPB)
density_kernel(const float* __restrict__ fm, float* __restrict__ out) {
    __shared__ __align__(1024) char sZ[TPB * 128];   // 16 KB feature chunk
    __shared__ uint2 sW[NKSTEP * 64];                // 18 KB B fragments
    __shared__ float sa2[KCOMP];

    int tid = threadIdx.x;
    int lane = tid & 31;
    int wid = tid >> 5;

    {   // stage B fragments + a'
        uint4* dst = (uint4*)sW;
        const uint4* src = (const uint4*)g_Wfrag;
#pragma unroll
        for (int i = 0; i < 9; ++i) dst[tid + i * TPB] = src[tid + i * TPB];
        if (tid < KCOMP) sa2[tid] = g_a2[tid];
    }

    size_t v0 = (size_t)blockIdx.x * TPB;
    float x[32];
    {
        const float4* xf = (const float4*)(fm + (v0 + tid) * 32);
#pragma unroll
        for (int q = 0; q < 8; ++q) {
            float4 t4 = xf[q];
            x[4 * q + 0] = t4.x; x[4 * q + 1] = t4.y;
            x[4 * q + 2] = t4.z; x[4 * q + 3] = t4.w;
        }
    }
    __syncthreads();

    uint32_t Zbase = smem_u32(sZ);
    uint32_t sts_row = Zbase + (uint32_t)tid * 128;
    uint32_t x7 = (uint32_t)(tid & 7);

    // ldmatrix per-lane bases: matrices 0..3 by lane octet
    uint32_t lrow0 = (uint32_t)(wid * 32 + (lane & 7) + ((lane >> 3) & 1) * 8);
    uint32_t lrow1 = lrow0 + 16;
    uint32_t colsel = (uint32_t)(lane >> 4);   // 0: k-cols 0-7, 1: k-cols 8-15
    uint32_t lad0 = Zbase + lrow0 * 128;
    uint32_t lad1 = Zbase + lrow1 * 128;
    uint32_t lx = lrow0 & 7;

    float acc[2][2][4];
#pragma unroll
    for (int a3 = 0; a3 < 2; ++a3)
#pragma unroll
        for (int b3 = 0; b3 < 2; ++b3)
#pragma unroll
            for (int c3 = 0; c3 < 4; ++c3) acc[a3][b3][c3] = 0.0f;

    float pend = 0.0f;
    uint32_t hh[4];

#define DO_CHUNK(cc) do {                                                      \
    __syncthreads();                                                           \
    _Pragma("unroll")                                                          \
    for (int _s = 0; _s < 4; ++_s) {                                           \
        int _sg = (cc) * 4 + _s;                                               \
        uint32_t _a0[4], _a1[4];                                               \
        uint32_t _cc = (uint32_t)(_s * 2) + colsel;                            \
        ldm4(_a0, lad0 + ((_cc ^ lx) << 4));                                   \
        ldm4(_a1, lad1 + ((_cc ^ lx) << 4));                                   \
        uint2 _b0 = sW[_sg * 64 + lane];                                       \
        uint2 _b1 = sW[_sg * 64 + 32 + lane];                                  \
        mma16816(acc[0][0], _a0, (uint32_t*)&_b0, acc[0][0]);                  \
        mma16816(acc[0][1], _a0, (uint32_t*)&_b1, acc[0][1]);                  \
        mma16816(acc[1][0], _a1, (uint32_t*)&_b0, acc[1][0]);                  \
        mma16816(acc[1][1], _a1, (uint32_t*)&_b1, acc[1][1]);                  \
    }                                                                          \
    __syncthreads();                                                           \
} while (0)

#define EMIT(tc, val) do {                                                     \
    const int _t = (tc); float _v = (val);                                     \
    if ((_t & 1) == 0) pend = _v;                                              \
    else {                                                                     \
        __half2 _h = __floats2half2_rn(pend, _v);                              \
        hh[(_t >> 1) & 3] = *(uint32_t*)&_h;                                   \
        if ((_t & 7) == 7) {                                                   \
            uint32_t _a = sts_row + (((((uint32_t)_t >> 3) & 7) ^ x7) << 4);   \
            STS128(hh[0], hh[1], hh[2], hh[3], _a);                            \
        }                                                                      \
        if ((_t & 63) == 63) DO_CHUNK(_t >> 6);                                \
    }                                                                          \
} while (0)

    // quadratic monomials t = i(i+1)/2 + j (i >= j)
#pragma unroll
    for (int i2 = 0; i2 < 32; ++i2)
#pragma unroll
        for (int j2 = 0; j2 <= i2; ++j2)
            EMIT(i2 * (i2 + 1) / 2 + j2, x[i2] * x[j2]);
    // linear monomials
#pragma unroll
    for (int j2 = 0; j2 < 32; ++j2) EMIT(528 + j2, x[j2]);
    // zero pad to 576 (final chunk fires at t = 575)
#pragma unroll
    for (int j2 = 0; j2 < 16; ++j2) EMIT(560 + j2, 0.0f);

#undef EMIT
#undef DO_CHUNK

    // epilogue: dens = sum_k a'_k exp(G)
    int g = lane >> 2, q = lane & 3;
    int c0 = q * 2;
    float w00 = sa2[c0], w01 = sa2[c0 + 1], w10 = sa2[c0 + 8], w11 = sa2[c0 + 9];
    float p0 = w00 * __expf(acc[0][0][0]) + w01 * __expf(acc[0][0][1])
             + w10 * __expf(acc[0][1][0]) + w11 * __expf(acc[0][1][1]);
    float p1 = w00 * __expf(acc[0][0][2]) + w01 * __expf(acc[0][0][3])
             + w10 * __expf(acc[0][1][2]) + w11 * __expf(acc[0][1][3]);
    float p2 = w00 * __expf(acc[1][0][0]) + w01 * __expf(acc[1][0][1])
             + w10 * __expf(acc[1][1][0]) + w11 * __expf(acc[1][1][1]);
    float p3 = w00 * __expf(acc[1][0][2]) + w01 * __expf(acc[1][0][3])
             + w10 * __expf(acc[1][1][2]) + w11 * __expf(acc[1][1][3]);

    p0 += __shfl_xor_sync(0xFFFFFFFFu, p0, 1); p0 += __shfl_xor_sync(0xFFFFFFFFu, p0, 2);
    p1 += __shfl_xor_sync(0xFFFFFFFFu, p1, 1); p1 += __shfl_xor_sync(0xFFFFFFFFu, p1, 2);
    p2 += __shfl_xor_sync(0xFFFFFFFFu, p2, 1); p2 += __shfl_xor_sync(0xFFFFFFFFu, p2, 2);
    p3 += __shfl_xor_sync(0xFFFFFFFFu, p3, 1); p3 += __shfl_xor_sync(0xFFFFFFFFu, p3, 2);

    if (q == 0) {
        size_t base = v0 + (size_t)wid * 32;
        size_t r0 = base + g, r1 = base + g + 8, r2 = base + g + 16, r3 = base + g + 24;
        out[r0] = ((r0 & 63) == 63) ? 0.0f : p0;
        out[r1] = ((r1 & 63) == 63) ? 0.0f : p1;
        out[r2] = ((r2 & 63) == 63) ? 0.0f : p2;
        out[r3] = ((r3 & 63) == 63) ? 0.0f : p3;
    }
}

// ---------------- launch ---------------------------------------------------
extern "C" void kernel_launch(void* const* d_in, const int* in_sizes, int n_in,
                              void* d_out, int out_size) {
    const float* fm   = (const float*)d_in[0];
    const float* wbg  = (const float*)d_in[1];
    const float* mubg = (const float*)d_in[2];
    const float* Lbg  = (const float*)d_in[3];
    const float* wfg  = (const float*)d_in[4];
    const float* mufg = (const float*)d_in[5];
    const float* Lfg  = (const float*)d_in[6];
    float* out = (float*)d_out;

    prep1_kernel<<<KCOMP, 32>>>(wbg, mubg, Lbg, wfg, mufg, Lfg);
    prep2_kernel<<<9, 256>>>();
    density_kernel<<<NTILES, TPB>>>(fm, out);
}